// round 5
// baseline (speedup 1.0000x reference)
#include <cuda_runtime.h>
#include <cuda_bf16.h>
#include <cstdint>

// Problem constants (fixed by reference)
#define VOCAB        100000
#define EMB_DIM      128
#define HIDDEN       256
#define NUM_CLASSES  20
#define B_SIZE       4096
#define S_LEN        200

#define ROWS         8                 // sequences per block (= warps per block)
#define GRID         (B_SIZE / ROWS)   // 512

typedef unsigned long long ull_t;

// packed fp32x2 fma: d = a * b + d
#define FMA2(d, a, b) \
    asm("fma.rn.f32x2 %0, %1, %2, %0;" : "+l"(d) : "l"(a), "l"(b))

__device__ __forceinline__ void unpack2(ull_t v, float& lo, float& hi) {
    asm("mov.b64 {%0, %1}, %2;" : "=f"(lo), "=f"(hi) : "l"(v));
}
__device__ __forceinline__ ull_t pack2(float lo, float hi) {
    ull_t v;
    asm("mov.b64 %0, {%1, %2};" : "=l"(v) : "f"(lo), "f"(hi));
    return v;
}

// ---------------------------------------------------------------------------
// Fused kernel: gather+pool -> layer1 (FFMA2, W1 from L1/L2) -> relu -> layer2
// Block: 256 threads = 8 warps; warp w pools sequence rb+w.
// Layer 1: thread = (rg = tid>>7 -> rows [4rg,4rg+4), cp = tid&127 -> cols
// {2cp,2cp+1}).  Weights: coalesced LDG.64 (W1 L1-resident).  Pooled: smem,
// pre-duplicated {p,p} so one broadcast LDS.128 feeds two k-steps of FFMA2.
// ---------------------------------------------------------------------------
__global__ void __launch_bounds__(256, 3) fused_kernel(
    const int*   __restrict__ x,        // [B, S]
    const int*   __restrict__ seq_len,  // [B]
    const float* __restrict__ emb,      // [VOCAB, 128]
    const float* __restrict__ W1,       // [128, 256] row-major
    const float* __restrict__ b1,       // [256]
    const float* __restrict__ W2,       // [256, 20]  row-major
    const float* __restrict__ b2,       // [20]
    float*       __restrict__ out)      // [B, 20]
{
    __shared__ float sp_dup[ROWS][2 * EMB_DIM];   // 8 KB  duplicated pooled
    __shared__ float sh[ROWS][HIDDEN];            // 8 KB  hidden

    const int tid  = threadIdx.x;
    const int warp = tid >> 5;
    const int lane = tid & 31;
    const int rb   = blockIdx.x * ROWS;

    // ================= Phase 1: gather + mean-pool (warp = one sequence) ====
    {
        const int b = rb + warp;
        const int L = seq_len[b];
        const int* xb = x + b * S_LEN;
        const float4* __restrict__ emb4 = reinterpret_cast<const float4*>(emb);

        float4 a0 = make_float4(0.f, 0.f, 0.f, 0.f);
        float4 a1 = make_float4(0.f, 0.f, 0.f, 0.f);
        float4 a2 = make_float4(0.f, 0.f, 0.f, 0.f);
        float4 a3 = make_float4(0.f, 0.f, 0.f, 0.f);

        int s = 0;
        for (; s + 4 <= L; s += 4) {          // 4 independent gathers in flight
            int t0 = __ldg(xb + s + 0);
            int t1 = __ldg(xb + s + 1);
            int t2 = __ldg(xb + s + 2);
            int t3 = __ldg(xb + s + 3);
            float4 v0 = __ldg(&emb4[(size_t)t0 * 32 + lane]);
            float4 v1 = __ldg(&emb4[(size_t)t1 * 32 + lane]);
            float4 v2 = __ldg(&emb4[(size_t)t2 * 32 + lane]);
            float4 v3 = __ldg(&emb4[(size_t)t3 * 32 + lane]);
            a0.x += v0.x; a0.y += v0.y; a0.z += v0.z; a0.w += v0.w;
            a1.x += v1.x; a1.y += v1.y; a1.z += v1.z; a1.w += v1.w;
            a2.x += v2.x; a2.y += v2.y; a2.z += v2.z; a2.w += v2.w;
            a3.x += v3.x; a3.y += v3.y; a3.z += v3.z; a3.w += v3.w;
        }
        for (; s < L; s++) {
            int t = __ldg(xb + s);
            float4 v = __ldg(&emb4[(size_t)t * 32 + lane]);
            a0.x += v.x; a0.y += v.y; a0.z += v.z; a0.w += v.w;
        }
        a0.x += a1.x; a0.y += a1.y; a0.z += a1.z; a0.w += a1.w;
        a2.x += a3.x; a2.y += a3.y; a2.z += a3.z; a2.w += a3.w;
        a0.x += a2.x; a0.y += a2.y; a0.z += a2.z; a0.w += a2.w;

        const float inv = 1.0f / (float)L;
        a0.x *= inv; a0.y *= inv; a0.z *= inv; a0.w *= inv;

        // write duplicated: lane l owns dims [4l, 4l+4) -> sp_dup[warp][8l..8l+8)
        float4* d = reinterpret_cast<float4*>(&sp_dup[warp][8 * lane]);
        d[0] = make_float4(a0.x, a0.x, a0.y, a0.y);
        d[1] = make_float4(a0.z, a0.z, a0.w, a0.w);
    }
    __syncthreads();

    // ================= Phase 2: layer 1 (pooled @ W1 + b1, relu) ============
    const int cp = tid & 127;        // column pair {2cp, 2cp+1}
    const int rg = tid >> 7;         // 0/1 -> rows [4rg, 4rg+4)
    const float* w1c = W1 + 2 * cp;

    ull_t acc[4];
    {
        const ull_t bp = *reinterpret_cast<const ull_t*>(b1 + 2 * cp);
        #pragma unroll
        for (int r = 0; r < 4; r++) acc[r] = bp;
    }

    #pragma unroll 4
    for (int k = 0; k < EMB_DIM; k += 2) {
        // coalesced 256 B/warp, W1 L1-resident after first touch
        ull_t w0 = __ldg(reinterpret_cast<const ull_t*>(w1c + (k + 0) * HIDDEN));
        ull_t w1 = __ldg(reinterpret_cast<const ull_t*>(w1c + (k + 1) * HIDDEN));
        #pragma unroll
        for (int r = 0; r < 4; r++) {
            // broadcast LDS.128: {p(k),p(k)},{p(k+1),p(k+1)}
            ulonglong2 pq = *reinterpret_cast<const ulonglong2*>(
                &sp_dup[rg * 4 + r][2 * k]);
            FMA2(acc[r], pq.x, w0);
            FMA2(acc[r], pq.y, w1);
        }
    }

    #pragma unroll
    for (int r = 0; r < 4; r++) {
        float lo, hi;
        unpack2(acc[r], lo, hi);
        lo = fmaxf(lo, 0.0f);
        hi = fmaxf(hi, 0.0f);
        *reinterpret_cast<ull_t*>(&sh[rg * 4 + r][2 * cp]) = pack2(lo, hi);
    }
    __syncthreads();

    // ================= Phase 3: layer 2 (hidden @ W2 + b2) ==================
    if (tid < ROWS * NUM_CLASSES) {          // 160 outputs
        const int r = tid / NUM_CLASSES;
        const int c = tid % NUM_CLASSES;
        const float* hrow = sh[r];
        float acc2 = b2[c];
        #pragma unroll 8
        for (int k = 0; k < HIDDEN; k++)
            acc2 = fmaf(hrow[k], __ldg(&W2[k * NUM_CLASSES + c]), acc2);
        out[(rb + r) * NUM_CLASSES + c] = acc2;
    }
}

// ---------------------------------------------------------------------------
// Inputs (metadata order): x[int32 B*S], seq_lengths[int32 B], emb[f32],
//                          W1[f32], b1[f32], W2[f32], b2[f32]
// Output: f32 [B, 20]
// ---------------------------------------------------------------------------
extern "C" void kernel_launch(void* const* d_in, const int* in_sizes, int n_in,
                              void* d_out, int out_size)
{
    const int*   x   = (const int*)  d_in[0];
    const int*   len = (const int*)  d_in[1];
    const float* emb = (const float*)d_in[2];
    const float* W1  = (const float*)d_in[3];
    const float* b1  = (const float*)d_in[4];
    const float* W2  = (const float*)d_in[5];
    const float* b2  = (const float*)d_in[6];
    float* out = (float*)d_out;

    fused_kernel<<<GRID, 256>>>(x, len, emb, W1, b1, W2, b2, out);
}

// round 6
// speedup vs baseline: 1.0795x; 1.0795x over previous
#include <cuda_runtime.h>
#include <cuda_bf16.h>
#include <cstdint>

// Problem constants (fixed by reference)
#define VOCAB        100000
#define EMB_DIM      128
#define HIDDEN       256
#define NUM_CLASSES  20
#define B_SIZE       4096
#define S_LEN        200

typedef unsigned long long ull_t;

// Scratch for pooled vectors: 4096 * 128 floats = 2 MB (static device array)
__device__ float g_pooled[B_SIZE * EMB_DIM];

// packed fp32x2 fma: d = a * b + d
#define FMA2(d, a, b) \
    asm("fma.rn.f32x2 %0, %1, %2, %0;" : "+l"(d) : "l"(a), "l"(b))

__device__ __forceinline__ void unpack2(ull_t v, float& lo, float& hi) {
    asm("mov.b64 {%0, %1}, %2;" : "=f"(lo), "=f"(hi) : "l"(v));
}
__device__ __forceinline__ ull_t pack2(float lo, float hi) {
    ull_t v;
    asm("mov.b64 %0, {%1, %2};" : "=l"(v) : "f"(lo), "f"(hi));
    return v;
}

// ---------------------------------------------------------------------------
// Kernel 1: embedding gather + masked mean pooling.
// One block (128 threads = 4 warps) per sequence -> perfect load balance
// across 4096 blocks.  Token ids staged in smem (kills the per-iter uniform
// LDG).  Warp w handles positions s = w + 4*i with 4-way unroll -> MLP=4
// gather rows in flight per warp; lane l owns dims [4l, 4l+4).
// ---------------------------------------------------------------------------
__global__ __launch_bounds__(128) void pool_kernel(
    const int* __restrict__ x,          // [B, S] token ids (int32)
    const int* __restrict__ seq_len,    // [B]
    const float* __restrict__ emb)      // [VOCAB, 128]
{
    __shared__ int    stok[S_LEN];
    __shared__ float4 red[4][32];

    const int b    = blockIdx.x;
    const int tid  = threadIdx.x;
    const int warp = tid >> 5;
    const int lane = tid & 31;

    const int L = seq_len[b];

    // stage token ids (coalesced, 2 passes)
    {
        const int* xb = x + b * S_LEN;
        if (tid < S_LEN)        stok[tid]       = xb[tid];
        if (tid + 128 < S_LEN)  stok[tid + 128] = xb[tid + 128];
    }
    __syncthreads();

    const float4* __restrict__ emb4 = reinterpret_cast<const float4*>(emb);

    float4 a0 = make_float4(0.f, 0.f, 0.f, 0.f);
    float4 a1 = make_float4(0.f, 0.f, 0.f, 0.f);
    float4 a2 = make_float4(0.f, 0.f, 0.f, 0.f);
    float4 a3 = make_float4(0.f, 0.f, 0.f, 0.f);

    int s = warp;
    for (; s + 12 < L; s += 16) {          // 4 independent gathers in flight
        int t0 = stok[s];
        int t1 = stok[s + 4];
        int t2 = stok[s + 8];
        int t3 = stok[s + 12];
        float4 v0 = __ldg(&emb4[(size_t)t0 * 32 + lane]);
        float4 v1 = __ldg(&emb4[(size_t)t1 * 32 + lane]);
        float4 v2 = __ldg(&emb4[(size_t)t2 * 32 + lane]);
        float4 v3 = __ldg(&emb4[(size_t)t3 * 32 + lane]);
        a0.x += v0.x; a0.y += v0.y; a0.z += v0.z; a0.w += v0.w;
        a1.x += v1.x; a1.y += v1.y; a1.z += v1.z; a1.w += v1.w;
        a2.x += v2.x; a2.y += v2.y; a2.z += v2.z; a2.w += v2.w;
        a3.x += v3.x; a3.y += v3.y; a3.z += v3.z; a3.w += v3.w;
    }
    for (; s < L; s += 4) {
        int t = stok[s];
        float4 v = __ldg(&emb4[(size_t)t * 32 + lane]);
        a0.x += v.x; a0.y += v.y; a0.z += v.z; a0.w += v.w;
    }
    a0.x += a1.x; a0.y += a1.y; a0.z += a1.z; a0.w += a1.w;
    a2.x += a3.x; a2.y += a3.y; a2.z += a3.z; a2.w += a3.w;
    a0.x += a2.x; a0.y += a2.y; a0.z += a2.z; a0.w += a2.w;

    red[warp][lane] = a0;
    __syncthreads();

    if (warp == 0) {
        float4 r0 = red[0][lane];
        float4 r1 = red[1][lane];
        float4 r2 = red[2][lane];
        float4 r3 = red[3][lane];
        float inv = 1.0f / (float)L;
        float4 o;
        o.x = (r0.x + r1.x + r2.x + r3.x) * inv;
        o.y = (r0.y + r1.y + r2.y + r3.y) * inv;
        o.z = (r0.z + r1.z + r2.z + r3.z) * inv;
        o.w = (r0.w + r1.w + r2.w + r3.w) * inv;
        reinterpret_cast<float4*>(g_pooled)[b * 32 + lane] = o;
    }
}

// ---------------------------------------------------------------------------
// Kernel 2: MLP.  hidden = relu(pooled @ W1 + b1); out = hidden @ W2 + b2
// 8 rows/block, 256 thr, 512 blocks (3/SM).  No weight staging: W1 read via
// coalesced LDG.64 and is L1-resident (128 KB).  Pooled rows duplicated in
// smem ({p,p}) so one broadcast LDS.128 feeds two FFMA2 k-steps.
// Thread: rg = tid>>7 -> rows [4rg,4rg+4); cp = tid&127 -> cols {2cp,2cp+1}.
// ---------------------------------------------------------------------------
#define MLP_ROWS 8

__global__ void __launch_bounds__(256, 3) mlp_kernel(
    const float* __restrict__ W1,   // [128, 256] row-major
    const float* __restrict__ b1,   // [256]
    const float* __restrict__ W2,   // [256, 20]  row-major
    const float* __restrict__ b2,   // [20]
    float* __restrict__ out)        // [B, 20]
{
    __shared__ float sp_dup[MLP_ROWS][2 * EMB_DIM];   // 8 KB
    __shared__ float sh[MLP_ROWS][HIDDEN];            // 8 KB

    const int tid = threadIdx.x;
    const int rb  = blockIdx.x * MLP_ROWS;

    // stage pooled rows, duplicated (256 float4 = 1/thread)
    {
        const float4 p = reinterpret_cast<const float4*>(g_pooled + rb * EMB_DIM)[tid];
        const int r  = tid >> 5;
        const int kb = (tid & 31) * 4;
        float4* d = reinterpret_cast<float4*>(&sp_dup[r][2 * kb]);
        d[0] = make_float4(p.x, p.x, p.y, p.y);
        d[1] = make_float4(p.z, p.z, p.w, p.w);
    }
    __syncthreads();

    const int cp = tid & 127;
    const int rg = tid >> 7;
    const float* w1c = W1 + 2 * cp;

    ull_t acc[4];
    {
        const ull_t bp = *reinterpret_cast<const ull_t*>(b1 + 2 * cp);
        #pragma unroll
        for (int r = 0; r < 4; r++) acc[r] = bp;
    }

    #pragma unroll 4
    for (int k = 0; k < EMB_DIM; k += 2) {
        ull_t w0 = __ldg(reinterpret_cast<const ull_t*>(w1c + (k + 0) * HIDDEN));
        ull_t w1 = __ldg(reinterpret_cast<const ull_t*>(w1c + (k + 1) * HIDDEN));
        #pragma unroll
        for (int r = 0; r < 4; r++) {
            ulonglong2 pq = *reinterpret_cast<const ulonglong2*>(
                &sp_dup[rg * 4 + r][2 * k]);
            FMA2(acc[r], pq.x, w0);
            FMA2(acc[r], pq.y, w1);
        }
    }

    #pragma unroll
    for (int r = 0; r < 4; r++) {
        float lo, hi;
        unpack2(acc[r], lo, hi);
        lo = fmaxf(lo, 0.0f);
        hi = fmaxf(hi, 0.0f);
        *reinterpret_cast<ull_t*>(&sh[rg * 4 + r][2 * cp]) = pack2(lo, hi);
    }
    __syncthreads();

    // layer 2: 8 rows x 20 classes = 160 dots of length 256
    if (tid < MLP_ROWS * NUM_CLASSES) {
        const int r = tid / NUM_CLASSES;
        const int c = tid % NUM_CLASSES;
        const float* hrow = sh[r];
        float acc2 = b2[c];
        #pragma unroll 8
        for (int k = 0; k < HIDDEN; k++)
            acc2 = fmaf(hrow[k], __ldg(&W2[k * NUM_CLASSES + c]), acc2);
        out[(rb + r) * NUM_CLASSES + c] = acc2;
    }
}

// ---------------------------------------------------------------------------
// Inputs (metadata order): x[int32 B*S], seq_lengths[int32 B], emb[f32],
//                          W1[f32], b1[f32], W2[f32], b2[f32]
// Output: f32 [B, 20]
// ---------------------------------------------------------------------------
extern "C" void kernel_launch(void* const* d_in, const int* in_sizes, int n_in,
                              void* d_out, int out_size)
{
    const int*   x   = (const int*)  d_in[0];
    const int*   len = (const int*)  d_in[1];
    const float* emb = (const float*)d_in[2];
    const float* W1  = (const float*)d_in[3];
    const float* b1  = (const float*)d_in[4];
    const float* W2  = (const float*)d_in[5];
    const float* b2  = (const float*)d_in[6];
    float* out = (float*)d_out;

    pool_kernel<<<B_SIZE, 128>>>(x, len, emb);
    mlp_kernel<<<B_SIZE / MLP_ROWS, 256>>>(W1, b1, W2, b2, out);
}

// round 9
// speedup vs baseline: 1.2393x; 1.1480x over previous
#include <cuda_runtime.h>
#include <cuda_bf16.h>
#include <cstdint>

// Problem constants (fixed by reference)
#define VOCAB        100000
#define EMB_DIM      128
#define HIDDEN       256
#define NUM_CLASSES  20
#define B_SIZE       4096
#define S_LEN        200

// Scratch for pooled vectors: 4096 * 128 floats = 2 MB (static device array)
__device__ float g_pooled[B_SIZE * EMB_DIM];

// ---------------------------------------------------------------------------
// Kernel 1: embedding gather + masked mean pooling.
// One block (128 threads = 4 warps) per sequence (perfect load balance).
// Warp w handles positions s = w + 4i; lane l owns dims [4l, 4l+4).
// 4-way unroll -> 4 outstanding LDG.128 per thread: ~32 KB gather bytes in
// flight per SM, enough to cover ~600cyc L2/DRAM latency at the LTS cap.
// ---------------------------------------------------------------------------
__global__ __launch_bounds__(128) void pool_kernel(
    const int* __restrict__ x,          // [B, S] token ids (int32)
    const int* __restrict__ seq_len,    // [B]
    const float* __restrict__ emb)      // [VOCAB, 128]
{
    const int b    = blockIdx.x;
    const int tid  = threadIdx.x;
    const int warp = tid >> 5;
    const int lane = tid & 31;

    const int L = seq_len[b];
    const int* xb = x + b * S_LEN;
    const float4* __restrict__ emb4 = reinterpret_cast<const float4*>(emb);

    float4 a0 = make_float4(0.f, 0.f, 0.f, 0.f);
    float4 a1 = make_float4(0.f, 0.f, 0.f, 0.f);
    float4 a2 = make_float4(0.f, 0.f, 0.f, 0.f);
    float4 a3 = make_float4(0.f, 0.f, 0.f, 0.f);

    int s = warp;
    for (; s + 12 < L; s += 16) {      // 4 independent gathers in flight
        int t0 = xb[s];
        int t1 = xb[s + 4];
        int t2 = xb[s + 8];
        int t3 = xb[s + 12];
        float4 v0 = __ldg(&emb4[(size_t)t0 * 32 + lane]);
        float4 v1 = __ldg(&emb4[(size_t)t1 * 32 + lane]);
        float4 v2 = __ldg(&emb4[(size_t)t2 * 32 + lane]);
        float4 v3 = __ldg(&emb4[(size_t)t3 * 32 + lane]);
        a0.x += v0.x; a0.y += v0.y; a0.z += v0.z; a0.w += v0.w;
        a1.x += v1.x; a1.y += v1.y; a1.z += v1.z; a1.w += v1.w;
        a2.x += v2.x; a2.y += v2.y; a2.z += v2.z; a2.w += v2.w;
        a3.x += v3.x; a3.y += v3.y; a3.z += v3.z; a3.w += v3.w;
    }
    for (; s < L; s += 4) {
        int t = xb[s];
        float4 v = __ldg(&emb4[(size_t)t * 32 + lane]);
        a0.x += v.x; a0.y += v.y; a0.z += v.z; a0.w += v.w;
    }
    a0.x += a1.x; a0.y += a1.y; a0.z += a1.z; a0.w += a1.w;
    a2.x += a3.x; a2.y += a3.y; a2.z += a3.z; a2.w += a3.w;
    a0.x += a2.x; a0.y += a2.y; a0.z += a2.z; a0.w += a2.w;

    __shared__ float4 red[4][32];
    red[warp][lane] = a0;
    __syncthreads();

    if (warp == 0) {
        float4 r0 = red[0][lane];
        float4 r1 = red[1][lane];
        float4 r2 = red[2][lane];
        float4 r3 = red[3][lane];
        float inv = 1.0f / (float)L;
        float4 o;
        o.x = (r0.x + r1.x + r2.x + r3.x) * inv;
        o.y = (r0.y + r1.y + r2.y + r3.y) * inv;
        o.z = (r0.z + r1.z + r2.z + r3.z) * inv;
        o.w = (r0.w + r1.w + r2.w + r3.w) * inv;
        reinterpret_cast<float4*>(g_pooled)[b * 32 + lane] = o;
    }
}

// ---------------------------------------------------------------------------
// Kernel 2: MLP (R1's proven variant, unchanged).
// 16 rows/block, 256 threads (thread j owns hidden column j).
// ---------------------------------------------------------------------------
#define MLP_ROWS 16

__global__ __launch_bounds__(256) void mlp_kernel(
    const float* __restrict__ W1,   // [128, 256] row-major
    const float* __restrict__ b1,   // [256]
    const float* __restrict__ W2,   // [256, 20]  row-major
    const float* __restrict__ b2,   // [20]
    float* __restrict__ out)        // [B, 20]
{
    __shared__ float sp[MLP_ROWS][EMB_DIM];      // pooled tile  (8 KB)
    __shared__ float sh[MLP_ROWS][HIDDEN];       // hidden tile (16 KB)

    const int tid = threadIdx.x;
    const int rb  = blockIdx.x * MLP_ROWS;

    // load 16 pooled rows (float4, coalesced)
    {
        const float4* src = reinterpret_cast<const float4*>(g_pooled + rb * EMB_DIM);
        float4* dst = reinterpret_cast<float4*>(&sp[0][0]);
        for (int i = tid; i < MLP_ROWS * EMB_DIM / 4; i += 256)
            dst[i] = src[i];
    }
    __syncthreads();

    // hidden layer: thread tid owns column j = tid of W1
    const int j = tid;
    float h[MLP_ROWS];
    const float bj = b1[j];
    #pragma unroll
    for (int r = 0; r < MLP_ROWS; r++) h[r] = bj;

    #pragma unroll 4
    for (int k = 0; k < EMB_DIM; k += 4) {
        float w0 = W1[(k + 0) * HIDDEN + j];
        float w1 = W1[(k + 1) * HIDDEN + j];
        float w2 = W1[(k + 2) * HIDDEN + j];
        float w3 = W1[(k + 3) * HIDDEN + j];
        #pragma unroll
        for (int r = 0; r < MLP_ROWS; r++) {
            float4 p = *reinterpret_cast<const float4*>(&sp[r][k]);  // smem broadcast
            h[r] = fmaf(p.x, w0, h[r]);
            h[r] = fmaf(p.y, w1, h[r]);
            h[r] = fmaf(p.z, w2, h[r]);
            h[r] = fmaf(p.w, w3, h[r]);
        }
    }
    #pragma unroll
    for (int r = 0; r < MLP_ROWS; r++)
        sh[r][j] = fmaxf(h[r], 0.0f);
    __syncthreads();

    // output layer: 16 rows x 20 classes = 320 dots of length 256
    for (int o = tid; o < MLP_ROWS * NUM_CLASSES; o += 256) {
        int r = o / NUM_CLASSES;
        int c = o % NUM_CLASSES;
        float acc = b2[c];
        #pragma unroll 8
        for (int k = 0; k < HIDDEN; k++)
            acc = fmaf(sh[r][k], W2[k * NUM_CLASSES + c], acc);
        out[(rb + r) * NUM_CLASSES + c] = acc;
    }
}

// ---------------------------------------------------------------------------
// Inputs (metadata order): x[int32 B*S], seq_lengths[int32 B], emb[f32],
//                          W1[f32], b1[f32], W2[f32], b2[f32]
// Output: f32 [B, 20]
// ---------------------------------------------------------------------------
extern "C" void kernel_launch(void* const* d_in, const int* in_sizes, int n_in,
                              void* d_out, int out_size)
{
    const int*   x   = (const int*)  d_in[0];
    const int*   len = (const int*)  d_in[1];
    const float* emb = (const float*)d_in[2];
    const float* W1  = (const float*)d_in[3];
    const float* b1  = (const float*)d_in[4];
    const float* W2  = (const float*)d_in[5];
    const float* b2  = (const float*)d_in[6];
    float* out = (float*)d_out;

    pool_kernel<<<B_SIZE, 128>>>(x, len, emb);
    mlp_kernel<<<B_SIZE / MLP_ROWS, 256>>>(W1, b1, W2, b2, out);
}

// round 11
// speedup vs baseline: 1.3032x; 1.0516x over previous
#include <cuda_runtime.h>
#include <cuda_bf16.h>
#include <cstdint>

// Problem constants (fixed by reference)
#define VOCAB        100000
#define EMB_DIM      128
#define HIDDEN       256
#define NUM_CLASSES  20
#define B_SIZE       4096
#define S_LEN        200

// Scratch for pooled vectors: 4096 * 128 floats = 2 MB (static device array)
__device__ float g_pooled[B_SIZE * EMB_DIM];

// ---------------------------------------------------------------------------
// Kernel 1: embedding gather + masked mean pooling.
// One block (128 threads = 4 warps) per sequence (perfect load balance).
// Token ids staged in smem once (kills per-iteration uniform-LDG latency on
// the address path).  Warp w handles positions s = w + 4i; lane l owns dims
// [4l, 4l+4).  6-way unroll -> 6 outstanding LDG.128 per thread: >=48 KB of
// gather bytes in flight per SM, covering ~600cyc latency at the LTS cap.
// ---------------------------------------------------------------------------
__global__ __launch_bounds__(128) void pool_kernel(
    const int* __restrict__ x,          // [B, S] token ids (int32)
    const int* __restrict__ seq_len,    // [B]
    const float* __restrict__ emb)      // [VOCAB, 128]
{
    __shared__ int    stok[S_LEN];
    __shared__ float4 red[4][32];

    const int b    = blockIdx.x;
    const int tid  = threadIdx.x;
    const int warp = tid >> 5;
    const int lane = tid & 31;

    const int L = seq_len[b];

    // stage token ids (coalesced, 2 passes of 128)
    {
        const int* xb = x + b * S_LEN;
        if (tid < S_LEN)       stok[tid]       = xb[tid];
        if (tid + 128 < S_LEN) stok[tid + 128] = xb[tid + 128];
    }
    __syncthreads();

    const float4* __restrict__ emb4 = reinterpret_cast<const float4*>(emb);

    float4 a0 = make_float4(0.f, 0.f, 0.f, 0.f);
    float4 a1 = make_float4(0.f, 0.f, 0.f, 0.f);
    float4 a2 = make_float4(0.f, 0.f, 0.f, 0.f);
    float4 a3 = make_float4(0.f, 0.f, 0.f, 0.f);
    float4 a4 = make_float4(0.f, 0.f, 0.f, 0.f);
    float4 a5 = make_float4(0.f, 0.f, 0.f, 0.f);

    int s = warp;
    for (; s + 20 < L; s += 24) {       // 6 independent gathers in flight
        int t0 = stok[s];
        int t1 = stok[s + 4];
        int t2 = stok[s + 8];
        int t3 = stok[s + 12];
        int t4 = stok[s + 16];
        int t5 = stok[s + 20];
        float4 v0 = __ldg(&emb4[(size_t)t0 * 32 + lane]);
        float4 v1 = __ldg(&emb4[(size_t)t1 * 32 + lane]);
        float4 v2 = __ldg(&emb4[(size_t)t2 * 32 + lane]);
        float4 v3 = __ldg(&emb4[(size_t)t3 * 32 + lane]);
        float4 v4 = __ldg(&emb4[(size_t)t4 * 32 + lane]);
        float4 v5 = __ldg(&emb4[(size_t)t5 * 32 + lane]);
        a0.x += v0.x; a0.y += v0.y; a0.z += v0.z; a0.w += v0.w;
        a1.x += v1.x; a1.y += v1.y; a1.z += v1.z; a1.w += v1.w;
        a2.x += v2.x; a2.y += v2.y; a2.z += v2.z; a2.w += v2.w;
        a3.x += v3.x; a3.y += v3.y; a3.z += v3.z; a3.w += v3.w;
        a4.x += v4.x; a4.y += v4.y; a4.z += v4.z; a4.w += v4.w;
        a5.x += v5.x; a5.y += v5.y; a5.z += v5.z; a5.w += v5.w;
    }
    for (; s < L; s += 4) {
        int t = stok[s];
        float4 v = __ldg(&emb4[(size_t)t * 32 + lane]);
        a0.x += v.x; a0.y += v.y; a0.z += v.z; a0.w += v.w;
    }
    a0.x += a1.x; a0.y += a1.y; a0.z += a1.z; a0.w += a1.w;
    a2.x += a3.x; a2.y += a3.y; a2.z += a3.z; a2.w += a3.w;
    a4.x += a5.x; a4.y += a5.y; a4.z += a5.z; a4.w += a5.w;
    a0.x += a2.x; a0.y += a2.y; a0.z += a2.z; a0.w += a2.w;
    a0.x += a4.x; a0.y += a4.y; a0.z += a4.z; a0.w += a4.w;

    red[warp][lane] = a0;
    __syncthreads();

    if (warp == 0) {
        float4 r0 = red[0][lane];
        float4 r1 = red[1][lane];
        float4 r2 = red[2][lane];
        float4 r3 = red[3][lane];
        float inv = 1.0f / (float)L;
        float4 o;
        o.x = (r0.x + r1.x + r2.x + r3.x) * inv;
        o.y = (r0.y + r1.y + r2.y + r3.y) * inv;
        o.z = (r0.z + r1.z + r2.z + r3.z) * inv;
        o.w = (r0.w + r1.w + r2.w + r3.w) * inv;
        reinterpret_cast<float4*>(g_pooled)[b * 32 + lane] = o;
    }
}

// ---------------------------------------------------------------------------
// Kernel 2: MLP.  16 rows/block, 256 threads (thread j owns hidden column j).
// Inner loop widened to k+=8: 8 W1 LDGs in flight -> halves exposed L2
// latency at low residency.  Otherwise identical to the proven R1 variant.
// ---------------------------------------------------------------------------
#define MLP_ROWS 16

__global__ __launch_bounds__(256) void mlp_kernel(
    const float* __restrict__ W1,   // [128, 256] row-major
    const float* __restrict__ b1,   // [256]
    const float* __restrict__ W2,   // [256, 20]  row-major
    const float* __restrict__ b2,   // [20]
    float* __restrict__ out)        // [B, 20]
{
    __shared__ float sp[MLP_ROWS][EMB_DIM];      // pooled tile  (8 KB)
    __shared__ float sh[MLP_ROWS][HIDDEN];       // hidden tile (16 KB)

    const int tid = threadIdx.x;
    const int rb  = blockIdx.x * MLP_ROWS;

    // load 16 pooled rows (float4, coalesced)
    {
        const float4* src = reinterpret_cast<const float4*>(g_pooled + rb * EMB_DIM);
        float4* dst = reinterpret_cast<float4*>(&sp[0][0]);
        for (int i = tid; i < MLP_ROWS * EMB_DIM / 4; i += 256)
            dst[i] = src[i];
    }
    __syncthreads();

    // hidden layer: thread tid owns column j = tid of W1
    const int j = tid;
    float h[MLP_ROWS];
    const float bj = b1[j];
    #pragma unroll
    for (int r = 0; r < MLP_ROWS; r++) h[r] = bj;

    #pragma unroll 1
    for (int k = 0; k < EMB_DIM; k += 8) {
        float w0 = W1[(k + 0) * HIDDEN + j];
        float w1 = W1[(k + 1) * HIDDEN + j];
        float w2 = W1[(k + 2) * HIDDEN + j];
        float w3 = W1[(k + 3) * HIDDEN + j];
        float w4 = W1[(k + 4) * HIDDEN + j];
        float w5 = W1[(k + 5) * HIDDEN + j];
        float w6 = W1[(k + 6) * HIDDEN + j];
        float w7 = W1[(k + 7) * HIDDEN + j];
        #pragma unroll
        for (int r = 0; r < MLP_ROWS; r++) {
            float4 p0 = *reinterpret_cast<const float4*>(&sp[r][k]);      // smem bcast
            float4 p1 = *reinterpret_cast<const float4*>(&sp[r][k + 4]);
            h[r] = fmaf(p0.x, w0, h[r]);
            h[r] = fmaf(p0.y, w1, h[r]);
            h[r] = fmaf(p0.z, w2, h[r]);
            h[r] = fmaf(p0.w, w3, h[r]);
            h[r] = fmaf(p1.x, w4, h[r]);
            h[r] = fmaf(p1.y, w5, h[r]);
            h[r] = fmaf(p1.z, w6, h[r]);
            h[r] = fmaf(p1.w, w7, h[r]);
        }
    }
    #pragma unroll
    for (int r = 0; r < MLP_ROWS; r++)
        sh[r][j] = fmaxf(h[r], 0.0f);
    __syncthreads();

    // output layer: 16 rows x 20 classes = 320 dots of length 256
    for (int o = tid; o < MLP_ROWS * NUM_CLASSES; o += 256) {
        int r = o / NUM_CLASSES;
        int c = o % NUM_CLASSES;
        float acc = b2[c];
        #pragma unroll 8
        for (int k = 0; k < HIDDEN; k++)
            acc = fmaf(sh[r][k], W2[k * NUM_CLASSES + c], acc);
        out[(rb + r) * NUM_CLASSES + c] = acc;
    }
}

// ---------------------------------------------------------------------------
// Inputs (metadata order): x[int32 B*S], seq_lengths[int32 B], emb[f32],
//                          W1[f32], b1[f32], W2[f32], b2[f32]
// Output: f32 [B, 20]
// ---------------------------------------------------------------------------
extern "C" void kernel_launch(void* const* d_in, const int* in_sizes, int n_in,
                              void* d_out, int out_size)
{
    const int*   x   = (const int*)  d_in[0];
    const int*   len = (const int*)  d_in[1];
    const float* emb = (const float*)d_in[2];
    const float* W1  = (const float*)d_in[3];
    const float* b1  = (const float*)d_in[4];
    const float* W2  = (const float*)d_in[5];
    const float* b2  = (const float*)d_in[6];
    float* out = (float*)d_out;

    pool_kernel<<<B_SIZE, 128>>>(x, len, emb);
    mlp_kernel<<<B_SIZE / MLP_ROWS, 256>>>(W1, b1, W2, b2, out);
}